// round 14
// baseline (speedup 1.0000x reference)
#include <cuda_runtime.h>
#include <cuda_bf16.h>
#include <cstdint>

// Problem shape (fixed by setup_inputs): B=8192 rows, D=256 dim.
#define BATCH 8192
#define DIM 256
#define INV_T 5.0f

#define BM 128
#define BN 128
#define NSPLIT 2
#define COLS_PER (BATCH / NSPLIT)   // 4096
#define NB_ITERS (COLS_PER / BN)    // 32
#define LDK (DIM + 8)               // 264 elems, 528B row stride -> conflict-free ldmatrix
#define TILE_BYTES (BM * LDK * 2)   // 67584
#define SMEM_TOTAL (3 * TILE_BYTES + 1024)

// Scratch (__device__ globals: allocations are forbidden)
__device__ __nv_bfloat16 g_ub[BATCH * DIM];   // normalized u * INV_T, bf16
__device__ __nv_bfloat16 g_pb[BATCH * DIM];   // normalized p, bf16
__device__ float g_pos[BATCH];                // diagonal sim (fp32 path)
__device__ float g_s[NSPLIT][BATCH];          // partial sum-exp per row

// ---------------------------------------------------------------------------
// PTX helpers
// ---------------------------------------------------------------------------
__device__ __forceinline__ uint32_t smem_u32(const void* p) {
    uint32_t a;
    asm("{ .reg .u64 t; cvta.to.shared.u64 t, %1; cvt.u32.u64 %0, t; }" : "=r"(a) : "l"(p));
    return a;
}
__device__ __forceinline__ void cp16(uint32_t s, const void* g) {
    asm volatile("cp.async.cg.shared.global [%0], [%1], 16;" :: "r"(s), "l"(g));
}
__device__ __forceinline__ void ldmx4(uint32_t* r, uint32_t addr) {
    asm volatile("ldmatrix.sync.aligned.m8n8.x4.shared.b16 {%0,%1,%2,%3}, [%4];"
        : "=r"(r[0]), "=r"(r[1]), "=r"(r[2]), "=r"(r[3]) : "r"(addr));
}
__device__ __forceinline__ void mma16816(float* d, const uint32_t* a, uint32_t b0, uint32_t b1) {
    asm volatile("mma.sync.aligned.m16n8k16.row.col.f32.bf16.bf16.f32 "
        "{%0,%1,%2,%3}, {%4,%5,%6,%7}, {%8,%9}, {%0,%1,%2,%3};"
        : "+f"(d[0]), "+f"(d[1]), "+f"(d[2]), "+f"(d[3])
        : "r"(a[0]), "r"(a[1]), "r"(a[2]), "r"(a[3]), "r"(b0), "r"(b1));
}

// packed f32x2 fma (Blackwell FFMA2 — confirmed to compile on this toolchain)
__device__ __forceinline__ unsigned long long fma2(unsigned long long a,
                                                   unsigned long long b,
                                                   unsigned long long c) {
    unsigned long long d;
    asm("fma.rn.f32x2 %0, %1, %2, %3;" : "=l"(d) : "l"(a), "l"(b), "l"(c));
    return d;
}
__device__ __forceinline__ unsigned long long pk2(float x) {
    uint32_t u = __float_as_uint(x);
    return ((unsigned long long)u << 32) | u;
}
__device__ __forceinline__ unsigned long long pack2(float lo, float hi) {
    unsigned long long v;
    asm("mov.b64 %0, {%1, %2};" : "=l"(v) : "f"(lo), "f"(hi));
    return v;
}

// Packed exp-and-accumulate on the FMA pipe. Valid |v| <= ~80; here |v| <= 5.3,
// so no max tracking / overflow handling is needed.
// 2^(v*log2e): magic-number rint, deg-4 2^f poly (rel err ~4e-5), exponent splice.
// 8 FFMA2 + 2 LEA per PAIR of values (vs ~20 scalar ops in the previous kernel).
__device__ __forceinline__ void expacc2(unsigned long long v, unsigned long long& s) {
    const unsigned long long K_L2E = pk2(1.4426950408889634f);
    const unsigned long long K_MAG = pk2(12582912.0f);      // 1.5 * 2^23
    const unsigned long long K_N1  = pk2(-1.0f);
    const unsigned long long K_C4  = pk2(0.0096181291f);
    const unsigned long long K_C3  = pk2(0.0555041087f);
    const unsigned long long K_C2  = pk2(0.2402265070f);
    const unsigned long long K_C1  = pk2(0.6931471806f);
    const unsigned long long K_1   = pk2(1.0f);

    unsigned long long z  = fma2(v, K_L2E, K_MAG);   // low 23 bits of each half = round(v*log2e)
    unsigned long long mz = fma2(z, K_N1, K_MAG);    // = -n (exact)
    unsigned long long f  = fma2(v, K_L2E, mz);      // frac in [-0.5, 0.5]
    uint32_t zl, zh;
    asm("mov.b64 {%0, %1}, %2;" : "=r"(zl), "=r"(zh) : "l"(z));
    uint32_t scl = (zl << 23) + 0x3f800000u;         // 2^n bit splice (LEA)
    uint32_t sch = (zh << 23) + 0x3f800000u;
    unsigned long long sc;
    asm("mov.b64 %0, {%1, %2};" : "=l"(sc) : "r"(scl), "r"(sch));
    unsigned long long p = fma2(K_C4, f, K_C3);
    p = fma2(p, f, K_C2);
    p = fma2(p, f, K_C1);
    p = fma2(p, f, K_1);
    s = fma2(p, sc, s);
}

// ---------------------------------------------------------------------------
// Kernel 1: per-row L2 normalize (fp32) -> bf16 outputs + fp32 diagonal.
// One warp per row, float4 loads, packed bf16x2 stores.
// ---------------------------------------------------------------------------
__global__ void __launch_bounds__(256) norm_pos_kernel(const float* __restrict__ uf,
                                                       const float* __restrict__ pf) {
    int row  = (blockIdx.x * blockDim.x + threadIdx.x) >> 5;
    int lane = threadIdx.x & 31;
    if (row >= BATCH) return;

    const float4* ur = (const float4*)(uf + (size_t)row * DIM);
    const float4* pr = (const float4*)(pf + (size_t)row * DIM);
    float4 a0 = ur[lane], a1 = ur[lane + 32];
    float4 b0 = pr[lane], b1 = pr[lane + 32];

    float su = 0.f, sp = 0.f, dp = 0.f;
#define ACC3(a, b) { su = fmaf(a, a, su); sp = fmaf(b, b, sp); dp = fmaf(a, b, dp); }
    ACC3(a0.x, b0.x) ACC3(a0.y, b0.y) ACC3(a0.z, b0.z) ACC3(a0.w, b0.w)
    ACC3(a1.x, b1.x) ACC3(a1.y, b1.y) ACC3(a1.z, b1.z) ACC3(a1.w, b1.w)
#undef ACC3
#pragma unroll
    for (int o = 16; o; o >>= 1) {
        su += __shfl_xor_sync(0xffffffffu, su, o);
        sp += __shfl_xor_sync(0xffffffffu, sp, o);
        dp += __shfl_xor_sync(0xffffffffu, dp, o);
    }
    float iu = 1.0f / fmaxf(sqrtf(su), 1e-12f);
    float ip = 1.0f / fmaxf(sqrtf(sp), 1e-12f);
    float us = iu * INV_T;   // fold 1/T into u so the MMA emits sim/T directly

#define BF2(d, x, y) asm("cvt.rn.bf16x2.f32 %0, %2, %1;" : "=r"(d) : "f"(x), "f"(y))
    uint2 w0, w1, v0, v1;
    BF2(w0.x, a0.x * us, a0.y * us); BF2(w0.y, a0.z * us, a0.w * us);
    BF2(w1.x, a1.x * us, a1.y * us); BF2(w1.y, a1.z * us, a1.w * us);
    BF2(v0.x, b0.x * ip, b0.y * ip); BF2(v0.y, b0.z * ip, b0.w * ip);
    BF2(v1.x, b1.x * ip, b1.y * ip); BF2(v1.y, b1.z * ip, b1.w * ip);
#undef BF2
    uint2* uo = (uint2*)(g_ub + (size_t)row * DIM);
    uint2* po = (uint2*)(g_pb + (size_t)row * DIM);
    uo[lane] = w0; uo[lane + 32] = w1;
    po[lane] = v0; po[lane + 32] = v1;
    if (lane == 0) g_pos[row] = dp * iu * ip * INV_T;
}

// ---------------------------------------------------------------------------
// Kernel 2: bf16 mma.sync GEMM (sim = (u/T)·p^T) fused with packed sum-exp.
// CTA tile 128x128, 8 warps 4(M)x2(N), warp tile 32x64 via m16n8k16.
// A tile resident in smem; B double-buffered full-K via cp.async.
// No max tracking: |sim/T| <= 5.3 a priori.
// ---------------------------------------------------------------------------
__global__ void __launch_bounds__(256) simlse_kernel() {
    extern __shared__ char smem[];
    const uint32_t sA = smem_u32(smem);
    const uint32_t sB = sA + TILE_BYTES;               // two B buffers follow A
    float* rbuf = (float*)(smem + 3 * TILE_BYTES);     // [2][128] cross-warp row sums

    const int tid  = threadIdx.x;
    const int lane = tid & 31;
    const int w    = tid >> 5;
    const int mg   = w >> 1;            // 0..3 : which 32-row slice
    const int ng   = w & 1;             // 0..1 : which 64-col slice
    const int rowBase = blockIdx.x * BM;
    const int colBase = blockIdx.y * COLS_PER;

    // --- cooperative tile loads: 128 rows x 256 bf16, 16B chunks ---
    const __nv_bfloat16* gA = g_ub + (size_t)rowBase * DIM;
#pragma unroll
    for (int i = 0; i < 16; i++) {
        int c = tid + i * 256, r = c >> 5, cc = c & 31;
        cp16(sA + (uint32_t)(r * LDK + cc * 8) * 2, gA + r * DIM + cc * 8);
    }
    {
        const __nv_bfloat16* gB = g_pb + (size_t)colBase * DIM;
#pragma unroll
        for (int i = 0; i < 16; i++) {
            int c = tid + i * 256, r = c >> 5, cc = c & 31;
            cp16(sB + (uint32_t)(r * LDK + cc * 8) * 2, gB + r * DIM + cc * 8);
        }
    }
    asm volatile("cp.async.commit_group;");

    // --- ldmatrix base addresses ---
    uint32_t aaddr[2];
#pragma unroll
    for (int m = 0; m < 2; m++)
        aaddr[m] = sA + (uint32_t)(((mg * 32 + m * 16 + (lane & 15)) * LDK + (lane >> 4) * 8) * 2);
    const int brow = (lane & 7) + ((lane >> 4) << 3);
    const int bcol = ((lane >> 3) & 1) * 8;
    uint32_t boff[4];
#pragma unroll
    for (int fp = 0; fp < 4; fp++)
        boff[fp] = (uint32_t)(((ng * 64 + fp * 16 + brow) * LDK + bcol) * 2);

    // packed row-sum accumulators: rows mg*32 + lane/4 + {0,8,16,24}
    unsigned long long spk[4] = {0ull, 0ull, 0ull, 0ull};

    for (int nb = 0; nb < NB_ITERS; nb++) {
        const int cur = nb & 1;
        if (nb + 1 < NB_ITERS) {
            const __nv_bfloat16* gB = g_pb + (size_t)(colBase + (nb + 1) * BN) * DIM;
            uint32_t dst = sB + (uint32_t)((cur ^ 1) * TILE_BYTES);
#pragma unroll
            for (int i = 0; i < 16; i++) {
                int c = tid + i * 256, r = c >> 5, cc = c & 31;
                cp16(dst + (uint32_t)(r * LDK + cc * 8) * 2, gB + r * DIM + cc * 8);
            }
            asm volatile("cp.async.commit_group;");
            asm volatile("cp.async.wait_group 1;");
        } else {
            asm volatile("cp.async.wait_group 0;");
        }
        __syncthreads();  // tile for this nb visible to all warps

        float acc[2][8][4];
#pragma unroll
        for (int m = 0; m < 2; m++)
#pragma unroll
            for (int f = 0; f < 8; f++)
#pragma unroll
                for (int j = 0; j < 4; j++) acc[m][f][j] = 0.f;

        const uint32_t Bu = sB + (uint32_t)(cur * TILE_BYTES);
#pragma unroll
        for (int ks = 0; ks < 16; ks++) {
            const uint32_t kadv = (uint32_t)(ks * 32);  // 16 bf16 = 32 bytes
            uint32_t a0[4], a1[4];
            ldmx4(a0, aaddr[0] + kadv);
            ldmx4(a1, aaddr[1] + kadv);
#pragma unroll
            for (int fp = 0; fp < 4; fp++) {
                uint32_t b[4];
                ldmx4(b, Bu + boff[fp] + kadv);
                mma16816(acc[0][2 * fp],     a0, b[0], b[1]);
                mma16816(acc[0][2 * fp + 1], a0, b[2], b[3]);
                mma16816(acc[1][2 * fp],     a1, b[0], b[1]);
                mma16816(acc[1][2 * fp + 1], a1, b[2], b[3]);
            }
        }
        __syncthreads();  // all warps done reading before next prefetch overwrites

        // fold this 128-col block into running sum-exp via packed FFMA2.
        // (d0,d1) share row r (adjacent cols); (d2,d3) share row r+8.
#pragma unroll
        for (int m = 0; m < 2; m++)
#pragma unroll
            for (int f = 0; f < 8; f++) {
                expacc2(pack2(acc[m][f][0], acc[m][f][1]), spk[2 * m]);
                expacc2(pack2(acc[m][f][2], acc[m][f][3]), spk[2 * m + 1]);
            }
    }

    // horizontal: each packed acc holds two partial col-sums of the SAME row
    float s[4];
#pragma unroll
    for (int i = 0; i < 4; i++) {
        uint32_t lo, hi;
        asm("mov.b64 {%0, %1}, %2;" : "=r"(lo), "=r"(hi) : "l"(spk[i]));
        s[i] = __uint_as_float(lo) + __uint_as_float(hi);
    }
    // merge across the quad (lanes sharing each row)
#pragma unroll
    for (int i = 0; i < 4; i++) {
        s[i] += __shfl_xor_sync(0xffffffffu, s[i], 1);
        s[i] += __shfl_xor_sync(0xffffffffu, s[i], 2);
    }
    if ((lane & 3) == 0) {
        int r = mg * 32 + (lane >> 2);
        rbuf[ng * 128 + r]      = s[0];
        rbuf[ng * 128 + r + 8]  = s[1];
        rbuf[ng * 128 + r + 16] = s[2];
        rbuf[ng * 128 + r + 24] = s[3];
    }
    __syncthreads();
    if (tid < 128)
        g_s[blockIdx.y][rowBase + tid] = rbuf[tid] + rbuf[128 + tid];
}

// ---------------------------------------------------------------------------
// Kernel 3: loss = mean(log(s0+s1) - pos)
// ---------------------------------------------------------------------------
__global__ void __launch_bounds__(256) finalize_kernel(float* __restrict__ out) {
    __shared__ float sm[256];
    float acc = 0.f;
    for (int i = threadIdx.x; i < BATCH; i += 256)
        acc += __logf(g_s[0][i] + g_s[1][i]) - g_pos[i];
    sm[threadIdx.x] = acc;
    __syncthreads();
#pragma unroll
    for (int w = 128; w > 0; w >>= 1) {
        if (threadIdx.x < w) sm[threadIdx.x] += sm[threadIdx.x + w];
        __syncthreads();
    }
    if (threadIdx.x == 0) out[0] = sm[0] * (1.0f / (float)BATCH);
}

// ---------------------------------------------------------------------------
extern "C" void kernel_launch(void* const* d_in, const int* in_sizes, int n_in,
                              void* d_out, int out_size) {
    const float* u = (const float*)d_in[0];
    const float* p = (const float*)d_in[1];
    float* out = (float*)d_out;

    cudaFuncSetAttribute(simlse_kernel, cudaFuncAttributeMaxDynamicSharedMemorySize, SMEM_TOTAL);

    norm_pos_kernel<<<(BATCH * 32) / 256, 256>>>(u, p);
    simlse_kernel<<<dim3(BATCH / BM, NSPLIT), 256, SMEM_TOTAL>>>();
    finalize_kernel<<<1, 256>>>(out);
}

// round 15
// speedup vs baseline: 1.0043x; 1.0043x over previous
#include <cuda_runtime.h>
#include <cuda_bf16.h>
#include <cstdint>

// Problem shape (fixed by setup_inputs): B=8192 rows, D=256 dim.
#define BATCH 8192
#define DIM 256
#define INV_T 5.0f

#define BM 128
#define BN 128
#define NSPLIT 2
#define COLS_PER (BATCH / NSPLIT)   // 4096
#define NB_ITERS (COLS_PER / BN)    // 32
#define LDKB 272                    // bytes/row in smem: 256 data + 16 pad (ldmatrix conflict-free)
#define TILE_BYTES (BM * LDKB)      // 34816
#define SMEM_TOTAL (3 * TILE_BYTES + 1024)

// Scratch (__device__ globals: allocations are forbidden)
__device__ uint8_t g_ub[BATCH * DIM];   // normalized u * INV_T, e4m3
__device__ uint8_t g_pb[BATCH * DIM];   // normalized p, e4m3
__device__ float g_pos[BATCH];          // diagonal sim/T (exact fp32 path)
__device__ float g_s[NSPLIT][BATCH];    // partial sum-exp per row

// ---------------------------------------------------------------------------
// PTX helpers
// ---------------------------------------------------------------------------
__device__ __forceinline__ uint32_t smem_u32(const void* p) {
    uint32_t a;
    asm("{ .reg .u64 t; cvta.to.shared.u64 t, %1; cvt.u32.u64 %0, t; }" : "=r"(a) : "l"(p));
    return a;
}
__device__ __forceinline__ void cp16(uint32_t s, const void* g) {
    asm volatile("cp.async.cg.shared.global [%0], [%1], 16;" :: "r"(s), "l"(g));
}
__device__ __forceinline__ void ldmx4(uint32_t* r, uint32_t addr) {
    asm volatile("ldmatrix.sync.aligned.m8n8.x4.shared.b16 {%0,%1,%2,%3}, [%4];"
        : "=r"(r[0]), "=r"(r[1]), "=r"(r[2]), "=r"(r[3]) : "r"(addr));
}
// FP8 e4m3 MMA: m16n8k32, fp32 accumulate. Fragment byte layout is identical
// to the bf16 m16n8k16 case (4B/lane per 8x8 ldmatrix tile), so the same
// ldmatrix addressing feeds it.
__device__ __forceinline__ void mma16832(float* d, const uint32_t* a, uint32_t b0, uint32_t b1) {
    asm volatile("mma.sync.aligned.m16n8k32.row.col.f32.e4m3.e4m3.f32 "
        "{%0,%1,%2,%3}, {%4,%5,%6,%7}, {%8,%9}, {%0,%1,%2,%3};"
        : "+f"(d[0]), "+f"(d[1]), "+f"(d[2]), "+f"(d[3])
        : "r"(a[0]), "r"(a[1]), "r"(a[2]), "r"(a[3]), "r"(b0), "r"(b1));
}

// packed f32x2 fma (Blackwell FFMA2)
__device__ __forceinline__ unsigned long long fma2(unsigned long long a,
                                                   unsigned long long b,
                                                   unsigned long long c) {
    unsigned long long d;
    asm("fma.rn.f32x2 %0, %1, %2, %3;" : "=l"(d) : "l"(a), "l"(b), "l"(c));
    return d;
}
__device__ __forceinline__ unsigned long long pk2(float x) {
    uint32_t u = __float_as_uint(x);
    return ((unsigned long long)u << 32) | u;
}
__device__ __forceinline__ unsigned long long pack2(float lo, float hi) {
    unsigned long long v;
    asm("mov.b64 %0, {%1, %2};" : "=l"(v) : "f"(lo), "f"(hi));
    return v;
}

// Packed exp-and-accumulate on the FMA pipe. Valid |v| <= ~80; here |v| <= ~5.7,
// so no max tracking / overflow handling is needed.
__device__ __forceinline__ void expacc2(unsigned long long v, unsigned long long& s) {
    const unsigned long long K_L2E = pk2(1.4426950408889634f);
    const unsigned long long K_MAG = pk2(12582912.0f);      // 1.5 * 2^23
    const unsigned long long K_N1  = pk2(-1.0f);
    const unsigned long long K_C4  = pk2(0.0096181291f);
    const unsigned long long K_C3  = pk2(0.0555041087f);
    const unsigned long long K_C2  = pk2(0.2402265070f);
    const unsigned long long K_C1  = pk2(0.6931471806f);
    const unsigned long long K_1   = pk2(1.0f);

    unsigned long long z  = fma2(v, K_L2E, K_MAG);   // low 23 bits of each half = round(v*log2e)
    unsigned long long mz = fma2(z, K_N1, K_MAG);    // = -n (exact)
    unsigned long long f  = fma2(v, K_L2E, mz);      // frac in [-0.5, 0.5]
    uint32_t zl, zh;
    asm("mov.b64 {%0, %1}, %2;" : "=r"(zl), "=r"(zh) : "l"(z));
    uint32_t scl = (zl << 23) + 0x3f800000u;         // 2^n bit splice
    uint32_t sch = (zh << 23) + 0x3f800000u;
    unsigned long long sc;
    asm("mov.b64 %0, {%1, %2};" : "=l"(sc) : "r"(scl), "r"(sch));
    unsigned long long p = fma2(K_C4, f, K_C3);
    p = fma2(p, f, K_C2);
    p = fma2(p, f, K_C1);
    p = fma2(p, f, K_1);
    s = fma2(p, sc, s);
}

// ---------------------------------------------------------------------------
// Kernel 1: per-row L2 normalize (fp32) -> e4m3 outputs + fp32 diagonal.
// One warp per row, float4 loads, packed e4m3x4 stores.
// ---------------------------------------------------------------------------
__global__ void __launch_bounds__(256) norm_pos_kernel(const float* __restrict__ uf,
                                                       const float* __restrict__ pf) {
    int row  = (blockIdx.x * blockDim.x + threadIdx.x) >> 5;
    int lane = threadIdx.x & 31;
    if (row >= BATCH) return;

    const float4* ur = (const float4*)(uf + (size_t)row * DIM);
    const float4* pr = (const float4*)(pf + (size_t)row * DIM);
    float4 a0 = ur[lane], a1 = ur[lane + 32];
    float4 b0 = pr[lane], b1 = pr[lane + 32];

    float su = 0.f, sp = 0.f, dp = 0.f;
#define ACC3(a, b) { su = fmaf(a, a, su); sp = fmaf(b, b, sp); dp = fmaf(a, b, dp); }
    ACC3(a0.x, b0.x) ACC3(a0.y, b0.y) ACC3(a0.z, b0.z) ACC3(a0.w, b0.w)
    ACC3(a1.x, b1.x) ACC3(a1.y, b1.y) ACC3(a1.z, b1.z) ACC3(a1.w, b1.w)
#undef ACC3
#pragma unroll
    for (int o = 16; o; o >>= 1) {
        su += __shfl_xor_sync(0xffffffffu, su, o);
        sp += __shfl_xor_sync(0xffffffffu, sp, o);
        dp += __shfl_xor_sync(0xffffffffu, dp, o);
    }
    float iu = 1.0f / fmaxf(sqrtf(su), 1e-12f);
    float ip = 1.0f / fmaxf(sqrtf(sp), 1e-12f);
    float us = iu * INV_T;   // fold 1/T into u so the MMA emits sim/T directly

    // pack 4 floats -> 4 e4m3 bytes (memory order: x,y,z,w)
#define E4M3X4(dst, v, s) do {                                                   \
        uint16_t _lo, _hi;                                                       \
        asm("cvt.rn.satfinite.e4m3x2.f32 %0, %2, %1;" : "=h"(_lo)                \
            : "f"((v).x * (s)), "f"((v).y * (s)));                               \
        asm("cvt.rn.satfinite.e4m3x2.f32 %0, %2, %1;" : "=h"(_hi)                \
            : "f"((v).z * (s)), "f"((v).w * (s)));                               \
        dst = ((uint32_t)_hi << 16) | (uint32_t)_lo;                             \
    } while (0)
    uint32_t w0, w1, v0, v1;
    E4M3X4(w0, a0, us); E4M3X4(w1, a1, us);
    E4M3X4(v0, b0, ip); E4M3X4(v1, b1, ip);
#undef E4M3X4
    uint32_t* uo = (uint32_t*)(g_ub + (size_t)row * DIM);
    uint32_t* po = (uint32_t*)(g_pb + (size_t)row * DIM);
    uo[lane] = w0; uo[lane + 32] = w1;
    po[lane] = v0; po[lane + 32] = v1;
    if (lane == 0) g_pos[row] = dp * iu * ip * INV_T;
}

// ---------------------------------------------------------------------------
// Kernel 2: e4m3 mma.sync GEMM (sim = (u/T)·p^T) fused with packed sum-exp.
// CTA tile 128x128, 8 warps 4(M)x2(N), warp tile 32x64 via m16n8k32.
// A tile resident in smem; B double-buffered full-K via cp.async.
// vs bf16 version: MMA/LDSM instruction counts and smem/L2 traffic all halve.
// ---------------------------------------------------------------------------
__global__ void __launch_bounds__(256) simlse_kernel() {
    extern __shared__ char smem[];
    const uint32_t sA = smem_u32(smem);
    const uint32_t sB = sA + TILE_BYTES;               // two B buffers follow A
    float* rbuf = (float*)(smem + 3 * TILE_BYTES);     // [2][128] cross-warp row sums

    const int tid  = threadIdx.x;
    const int lane = tid & 31;
    const int w    = tid >> 5;
    const int mg   = w >> 1;            // 0..3 : which 32-row slice
    const int ng   = w & 1;             // 0..1 : which 64-col slice
    const int rowBase = blockIdx.x * BM;
    const int colBase = blockIdx.y * COLS_PER;

    // --- cooperative tile loads: 128 rows x 256 bytes, 16B chunks, 8/thread ---
    const uint8_t* gA = g_ub + (size_t)rowBase * DIM;
#pragma unroll
    for (int i = 0; i < 8; i++) {
        int c = tid + i * 256, r = c >> 4, cc = c & 15;
        cp16(sA + (uint32_t)(r * LDKB + cc * 16), gA + (size_t)r * DIM + cc * 16);
    }
    {
        const uint8_t* gB = g_pb + (size_t)colBase * DIM;
#pragma unroll
        for (int i = 0; i < 8; i++) {
            int c = tid + i * 256, r = c >> 4, cc = c & 15;
            cp16(sB + (uint32_t)(r * LDKB + cc * 16), gB + (size_t)r * DIM + cc * 16);
        }
    }
    asm volatile("cp.async.commit_group;");

    // --- ldmatrix base addresses (byte-identical mapping to the bf16 case) ---
    uint32_t aaddr[2];
#pragma unroll
    for (int m = 0; m < 2; m++)
        aaddr[m] = sA + (uint32_t)((mg * 32 + m * 16 + (lane & 15)) * LDKB + (lane >> 4) * 16);
    const int brow = (lane & 7) + ((lane >> 4) << 3);
    const int bcol = ((lane >> 3) & 1) * 16;           // byte offset
    uint32_t boff[4];
#pragma unroll
    for (int fp = 0; fp < 4; fp++)
        boff[fp] = (uint32_t)((ng * 64 + fp * 16 + brow) * LDKB + bcol);

    // packed row-sum accumulators: rows mg*32 + lane/4 + {0,8,16,24}
    unsigned long long spk[4] = {0ull, 0ull, 0ull, 0ull};

    for (int nb = 0; nb < NB_ITERS; nb++) {
        const int cur = nb & 1;
        if (nb + 1 < NB_ITERS) {
            const uint8_t* gB = g_pb + (size_t)(colBase + (nb + 1) * BN) * DIM;
            uint32_t dst = sB + (uint32_t)((cur ^ 1) * TILE_BYTES);
#pragma unroll
            for (int i = 0; i < 8; i++) {
                int c = tid + i * 256, r = c >> 4, cc = c & 15;
                cp16(dst + (uint32_t)(r * LDKB + cc * 16), gB + (size_t)r * DIM + cc * 16);
            }
            asm volatile("cp.async.commit_group;");
            asm volatile("cp.async.wait_group 1;");
        } else {
            asm volatile("cp.async.wait_group 0;");
        }
        __syncthreads();  // tile for this nb visible to all warps

        float acc[2][8][4];
#pragma unroll
        for (int m = 0; m < 2; m++)
#pragma unroll
            for (int f = 0; f < 8; f++)
#pragma unroll
                for (int j = 0; j < 4; j++) acc[m][f][j] = 0.f;

        const uint32_t Bu = sB + (uint32_t)(cur * TILE_BYTES);
#pragma unroll
        for (int ks = 0; ks < 8; ks++) {               // k32 per step: 8 steps cover D=256
            const uint32_t kadv = (uint32_t)(ks * 32); // 32 e4m3 = 32 bytes
            uint32_t a0[4], a1[4];
            ldmx4(a0, aaddr[0] + kadv);
            ldmx4(a1, aaddr[1] + kadv);
#pragma unroll
            for (int fp = 0; fp < 4; fp++) {
                uint32_t b[4];
                ldmx4(b, Bu + boff[fp] + kadv);
                mma16832(acc[0][2 * fp],     a0, b[0], b[1]);
                mma16832(acc[0][2 * fp + 1], a0, b[2], b[3]);
                mma16832(acc[1][2 * fp],     a1, b[0], b[1]);
                mma16832(acc[1][2 * fp + 1], a1, b[2], b[3]);
            }
        }
        __syncthreads();  // all warps done reading before next prefetch overwrites

        // fold this 128-col block into running sum-exp via packed FFMA2.
        // (d0,d1) share row r (adjacent cols); (d2,d3) share row r+8.
#pragma unroll
        for (int m = 0; m < 2; m++)
#pragma unroll
            for (int f = 0; f < 8; f++) {
                expacc2(pack2(acc[m][f][0], acc[m][f][1]), spk[2 * m]);
                expacc2(pack2(acc[m][f][2], acc[m][f][3]), spk[2 * m + 1]);
            }
    }

    // horizontal: each packed acc holds two partial col-sums of the SAME row
    float s[4];
#pragma unroll
    for (int i = 0; i < 4; i++) {
        uint32_t lo, hi;
        asm("mov.b64 {%0, %1}, %2;" : "=r"(lo), "=r"(hi) : "l"(spk[i]));
        s[i] = __uint_as_float(lo) + __uint_as_float(hi);
    }
    // merge across the quad (lanes sharing each row)
#pragma unroll
    for (int i = 0; i < 4; i++) {
        s[i] += __shfl_xor_sync(0xffffffffu, s[i], 1);
        s[i] += __shfl_xor_sync(0xffffffffu, s[i], 2);
    }
    if ((lane & 3) == 0) {
        int r = mg * 32 + (lane >> 2);
        rbuf[ng * 128 + r]      = s[0];
        rbuf[ng * 128 + r + 8]  = s[1];
        rbuf[ng * 128 + r + 16] = s[2];
        rbuf[ng * 128 + r + 24] = s[3];
    }
    __syncthreads();
    if (tid < 128)
        g_s[blockIdx.y][rowBase + tid] = rbuf[tid] + rbuf[128 + tid];
}

// ---------------------------------------------------------------------------
// Kernel 3: loss = mean(log(s0+s1) - pos)
// ---------------------------------------------------------------------------
__global__ void __launch_bounds__(256) finalize_kernel(float* __restrict__ out) {
    __shared__ float sm[256];
    float acc = 0.f;
    for (int i = threadIdx.x; i < BATCH; i += 256)
        acc += __logf(g_s[0][i] + g_s[1][i]) - g_pos[i];
    sm[threadIdx.x] = acc;
    __syncthreads();
#pragma unroll
    for (int w = 128; w > 0; w >>= 1) {
        if (threadIdx.x < w) sm[threadIdx.x] += sm[threadIdx.x + w];
        __syncthreads();
    }
    if (threadIdx.x == 0) out[0] = sm[0] * (1.0f / (float)BATCH);
}

// ---------------------------------------------------------------------------
extern "C" void kernel_launch(void* const* d_in, const int* in_sizes, int n_in,
                              void* d_out, int out_size) {
    const float* u = (const float*)d_in[0];
    const float* p = (const float*)d_in[1];
    float* out = (float*)d_out;

    cudaFuncSetAttribute(simlse_kernel, cudaFuncAttributeMaxDynamicSharedMemorySize, SMEM_TOTAL);

    norm_pos_kernel<<<(BATCH * 32) / 256, 256>>>(u, p);
    simlse_kernel<<<dim3(BATCH / BM, NSPLIT), 256, SMEM_TOTAL>>>();
    finalize_kernel<<<1, 256>>>(out);
}

// round 16
// speedup vs baseline: 1.0050x; 1.0007x over previous
#include <cuda_runtime.h>
#include <cuda_bf16.h>
#include <cstdint>

// Problem shape (fixed by setup_inputs): B=8192 rows, D=256 dim.
#define BATCH 8192
#define DIM 256
#define INV_T 5.0f

#define BM 128
#define BN 128
#define NSPLIT 2
#define COLS_PER (BATCH / NSPLIT)   // 4096
#define NB_ITERS (COLS_PER / BN)    // 32
#define LDKB 272                    // bytes/row in smem: 256 data + 16 pad (ldmatrix conflict-free)
#define TILE_BYTES (BM * LDKB)      // 34816
#define SMEM_TOTAL (3 * TILE_BYTES + 1024)

// Scratch (__device__ globals: allocations are forbidden)
__device__ uint8_t g_ub[BATCH * DIM];   // normalized u * INV_T, e4m3
__device__ uint8_t g_pb[BATCH * DIM];   // normalized p, e4m3
__device__ float g_pos[BATCH];          // diagonal sim/T (exact fp32 path)
__device__ float g_s[NSPLIT][BATCH];    // partial sum-exp per row

// ---------------------------------------------------------------------------
// PTX helpers
// ---------------------------------------------------------------------------
__device__ __forceinline__ uint32_t smem_u32(const void* p) {
    uint32_t a;
    asm("{ .reg .u64 t; cvta.to.shared.u64 t, %1; cvt.u32.u64 %0, t; }" : "=r"(a) : "l"(p));
    return a;
}
__device__ __forceinline__ void cp16(uint32_t s, const void* g) {
    asm volatile("cp.async.cg.shared.global [%0], [%1], 16;" :: "r"(s), "l"(g));
}
__device__ __forceinline__ void ldmx4(uint32_t* r, uint32_t addr) {
    asm volatile("ldmatrix.sync.aligned.m8n8.x4.shared.b16 {%0,%1,%2,%3}, [%4];"
        : "=r"(r[0]), "=r"(r[1]), "=r"(r[2]), "=r"(r[3]) : "r"(addr));
}
// FP8 e4m3 MMA: m16n8k32, fp32 accumulate. Fragment byte layout is identical
// to the bf16 m16n8k16 case (4B/lane per 8x8 ldmatrix tile), so the same
// ldmatrix addressing feeds it.
__device__ __forceinline__ void mma16832(float* d, const uint32_t* a, uint32_t b0, uint32_t b1) {
    asm volatile("mma.sync.aligned.m16n8k32.row.col.f32.e4m3.e4m3.f32 "
        "{%0,%1,%2,%3}, {%4,%5,%6,%7}, {%8,%9}, {%0,%1,%2,%3};"
        : "+f"(d[0]), "+f"(d[1]), "+f"(d[2]), "+f"(d[3])
        : "r"(a[0]), "r"(a[1]), "r"(a[2]), "r"(a[3]), "r"(b0), "r"(b1));
}

// packed f32x2 fma (Blackwell FFMA2)
__device__ __forceinline__ unsigned long long fma2(unsigned long long a,
                                                   unsigned long long b,
                                                   unsigned long long c) {
    unsigned long long d;
    asm("fma.rn.f32x2 %0, %1, %2, %3;" : "=l"(d) : "l"(a), "l"(b), "l"(c));
    return d;
}
__device__ __forceinline__ unsigned long long pk2(float x) {
    uint32_t u = __float_as_uint(x);
    return ((unsigned long long)u << 32) | u;
}
__device__ __forceinline__ unsigned long long pack2(float lo, float hi) {
    unsigned long long v;
    asm("mov.b64 %0, {%1, %2};" : "=l"(v) : "f"(lo), "f"(hi));
    return v;
}

// Packed exp-and-accumulate on the FMA pipe. Valid |v| <= ~80; here |v| <= ~5.7,
// so no max tracking / overflow handling is needed.
__device__ __forceinline__ void expacc2(unsigned long long v, unsigned long long& s) {
    const unsigned long long K_L2E = pk2(1.4426950408889634f);
    const unsigned long long K_MAG = pk2(12582912.0f);      // 1.5 * 2^23
    const unsigned long long K_N1  = pk2(-1.0f);
    const unsigned long long K_C4  = pk2(0.0096181291f);
    const unsigned long long K_C3  = pk2(0.0555041087f);
    const unsigned long long K_C2  = pk2(0.2402265070f);
    const unsigned long long K_C1  = pk2(0.6931471806f);
    const unsigned long long K_1   = pk2(1.0f);

    unsigned long long z  = fma2(v, K_L2E, K_MAG);   // low 23 bits of each half = round(v*log2e)
    unsigned long long mz = fma2(z, K_N1, K_MAG);    // = -n (exact)
    unsigned long long f  = fma2(v, K_L2E, mz);      // frac in [-0.5, 0.5]
    uint32_t zl, zh;
    asm("mov.b64 {%0, %1}, %2;" : "=r"(zl), "=r"(zh) : "l"(z));
    uint32_t scl = (zl << 23) + 0x3f800000u;         // 2^n bit splice
    uint32_t sch = (zh << 23) + 0x3f800000u;
    unsigned long long sc;
    asm("mov.b64 %0, {%1, %2};" : "=l"(sc) : "r"(scl), "r"(sch));
    unsigned long long p = fma2(K_C4, f, K_C3);
    p = fma2(p, f, K_C2);
    p = fma2(p, f, K_C1);
    p = fma2(p, f, K_1);
    s = fma2(p, sc, s);
}

// ---------------------------------------------------------------------------
// Kernel 1: per-row L2 normalize (fp32) -> e4m3 outputs + fp32 diagonal.
// One warp per row, float4 loads, packed e4m3x4 stores.
// ---------------------------------------------------------------------------
__global__ void __launch_bounds__(256) norm_pos_kernel(const float* __restrict__ uf,
                                                       const float* __restrict__ pf) {
    int row  = (blockIdx.x * blockDim.x + threadIdx.x) >> 5;
    int lane = threadIdx.x & 31;
    if (row >= BATCH) return;

    const float4* ur = (const float4*)(uf + (size_t)row * DIM);
    const float4* pr = (const float4*)(pf + (size_t)row * DIM);
    float4 a0 = ur[lane], a1 = ur[lane + 32];
    float4 b0 = pr[lane], b1 = pr[lane + 32];

    float su = 0.f, sp = 0.f, dp = 0.f;
#define ACC3(a, b) { su = fmaf(a, a, su); sp = fmaf(b, b, sp); dp = fmaf(a, b, dp); }
    ACC3(a0.x, b0.x) ACC3(a0.y, b0.y) ACC3(a0.z, b0.z) ACC3(a0.w, b0.w)
    ACC3(a1.x, b1.x) ACC3(a1.y, b1.y) ACC3(a1.z, b1.z) ACC3(a1.w, b1.w)
#undef ACC3
#pragma unroll
    for (int o = 16; o; o >>= 1) {
        su += __shfl_xor_sync(0xffffffffu, su, o);
        sp += __shfl_xor_sync(0xffffffffu, sp, o);
        dp += __shfl_xor_sync(0xffffffffu, dp, o);
    }
    float iu = 1.0f / fmaxf(sqrtf(su), 1e-12f);
    float ip = 1.0f / fmaxf(sqrtf(sp), 1e-12f);
    float us = iu * INV_T;   // fold 1/T into u so the MMA emits sim/T directly

    // pack 4 floats -> 4 e4m3 bytes (memory order: x,y,z,w)
#define E4M3X4(dst, v, s) do {                                                   \
        uint16_t _lo, _hi;                                                       \
        asm("cvt.rn.satfinite.e4m3x2.f32 %0, %2, %1;" : "=h"(_lo)                \
            : "f"((v).x * (s)), "f"((v).y * (s)));                               \
        asm("cvt.rn.satfinite.e4m3x2.f32 %0, %2, %1;" : "=h"(_hi)                \
            : "f"((v).z * (s)), "f"((v).w * (s)));                               \
        dst = ((uint32_t)_hi << 16) | (uint32_t)_lo;                             \
    } while (0)
    uint32_t w0, w1, v0, v1;
    E4M3X4(w0, a0, us); E4M3X4(w1, a1, us);
    E4M3X4(v0, b0, ip); E4M3X4(v1, b1, ip);
#undef E4M3X4
    uint32_t* uo = (uint32_t*)(g_ub + (size_t)row * DIM);
    uint32_t* po = (uint32_t*)(g_pb + (size_t)row * DIM);
    uo[lane] = w0; uo[lane + 32] = w1;
    po[lane] = v0; po[lane + 32] = v1;
    if (lane == 0) g_pos[row] = dp * iu * ip * INV_T;
}

// ---------------------------------------------------------------------------
// Kernel 2: e4m3 mma.sync GEMM (sim = (u/T)·p^T) fused with packed sum-exp.
// CTA tile 128x128, 8 warps 4(M)x2(N), warp tile 32x64 via m16n8k32.
// A tile resident in smem; B double-buffered full-K via cp.async.
// vs bf16 version: MMA/LDSM instruction counts and smem/L2 traffic all halve.
// ---------------------------------------------------------------------------
__global__ void __launch_bounds__(256) simlse_kernel() {
    extern __shared__ char smem[];
    const uint32_t sA = smem_u32(smem);
    const uint32_t sB = sA + TILE_BYTES;               // two B buffers follow A
    float* rbuf = (float*)(smem + 3 * TILE_BYTES);     // [2][128] cross-warp row sums

    const int tid  = threadIdx.x;
    const int lane = tid & 31;
    const int w    = tid >> 5;
    const int mg   = w >> 1;            // 0..3 : which 32-row slice
    const int ng   = w & 1;             // 0..1 : which 64-col slice
    const int rowBase = blockIdx.x * BM;
    const int colBase = blockIdx.y * COLS_PER;

    // --- cooperative tile loads: 128 rows x 256 bytes, 16B chunks, 8/thread ---
    const uint8_t* gA = g_ub + (size_t)rowBase * DIM;
#pragma unroll
    for (int i = 0; i < 8; i++) {
        int c = tid + i * 256, r = c >> 4, cc = c & 15;
        cp16(sA + (uint32_t)(r * LDKB + cc * 16), gA + (size_t)r * DIM + cc * 16);
    }
    {
        const uint8_t* gB = g_pb + (size_t)colBase * DIM;
#pragma unroll
        for (int i = 0; i < 8; i++) {
            int c = tid + i * 256, r = c >> 4, cc = c & 15;
            cp16(sB + (uint32_t)(r * LDKB + cc * 16), gB + (size_t)r * DIM + cc * 16);
        }
    }
    asm volatile("cp.async.commit_group;");

    // --- ldmatrix base addresses (byte-identical mapping to the bf16 case) ---
    uint32_t aaddr[2];
#pragma unroll
    for (int m = 0; m < 2; m++)
        aaddr[m] = sA + (uint32_t)((mg * 32 + m * 16 + (lane & 15)) * LDKB + (lane >> 4) * 16);
    const int brow = (lane & 7) + ((lane >> 4) << 3);
    const int bcol = ((lane >> 3) & 1) * 16;           // byte offset
    uint32_t boff[4];
#pragma unroll
    for (int fp = 0; fp < 4; fp++)
        boff[fp] = (uint32_t)((ng * 64 + fp * 16 + brow) * LDKB + bcol);

    // packed row-sum accumulators: rows mg*32 + lane/4 + {0,8,16,24}
    unsigned long long spk[4] = {0ull, 0ull, 0ull, 0ull};

    for (int nb = 0; nb < NB_ITERS; nb++) {
        const int cur = nb & 1;
        if (nb + 1 < NB_ITERS) {
            const uint8_t* gB = g_pb + (size_t)(colBase + (nb + 1) * BN) * DIM;
            uint32_t dst = sB + (uint32_t)((cur ^ 1) * TILE_BYTES);
#pragma unroll
            for (int i = 0; i < 8; i++) {
                int c = tid + i * 256, r = c >> 4, cc = c & 15;
                cp16(dst + (uint32_t)(r * LDKB + cc * 16), gB + (size_t)r * DIM + cc * 16);
            }
            asm volatile("cp.async.commit_group;");
            asm volatile("cp.async.wait_group 1;");
        } else {
            asm volatile("cp.async.wait_group 0;");
        }
        __syncthreads();  // tile for this nb visible to all warps

        float acc[2][8][4];
#pragma unroll
        for (int m = 0; m < 2; m++)
#pragma unroll
            for (int f = 0; f < 8; f++)
#pragma unroll
                for (int j = 0; j < 4; j++) acc[m][f][j] = 0.f;

        const uint32_t Bu = sB + (uint32_t)(cur * TILE_BYTES);
#pragma unroll
        for (int ks = 0; ks < 8; ks++) {               // k32 per step: 8 steps cover D=256
            const uint32_t kadv = (uint32_t)(ks * 32); // 32 e4m3 = 32 bytes
            uint32_t a0[4], a1[4];
            ldmx4(a0, aaddr[0] + kadv);
            ldmx4(a1, aaddr[1] + kadv);
#pragma unroll
            for (int fp = 0; fp < 4; fp++) {
                uint32_t b[4];
                ldmx4(b, Bu + boff[fp] + kadv);
                mma16832(acc[0][2 * fp],     a0, b[0], b[1]);
                mma16832(acc[0][2 * fp + 1], a0, b[2], b[3]);
                mma16832(acc[1][2 * fp],     a1, b[0], b[1]);
                mma16832(acc[1][2 * fp + 1], a1, b[2], b[3]);
            }
        }
        __syncthreads();  // all warps done reading before next prefetch overwrites

        // fold this 128-col block into running sum-exp via packed FFMA2.
        // (d0,d1) share row r (adjacent cols); (d2,d3) share row r+8.
#pragma unroll
        for (int m = 0; m < 2; m++)
#pragma unroll
            for (int f = 0; f < 8; f++) {
                expacc2(pack2(acc[m][f][0], acc[m][f][1]), spk[2 * m]);
                expacc2(pack2(acc[m][f][2], acc[m][f][3]), spk[2 * m + 1]);
            }
    }

    // horizontal: each packed acc holds two partial col-sums of the SAME row
    float s[4];
#pragma unroll
    for (int i = 0; i < 4; i++) {
        uint32_t lo, hi;
        asm("mov.b64 {%0, %1}, %2;" : "=r"(lo), "=r"(hi) : "l"(spk[i]));
        s[i] = __uint_as_float(lo) + __uint_as_float(hi);
    }
    // merge across the quad (lanes sharing each row)
#pragma unroll
    for (int i = 0; i < 4; i++) {
        s[i] += __shfl_xor_sync(0xffffffffu, s[i], 1);
        s[i] += __shfl_xor_sync(0xffffffffu, s[i], 2);
    }
    if ((lane & 3) == 0) {
        int r = mg * 32 + (lane >> 2);
        rbuf[ng * 128 + r]      = s[0];
        rbuf[ng * 128 + r + 8]  = s[1];
        rbuf[ng * 128 + r + 16] = s[2];
        rbuf[ng * 128 + r + 24] = s[3];
    }
    __syncthreads();
    if (tid < 128)
        g_s[blockIdx.y][rowBase + tid] = rbuf[tid] + rbuf[128 + tid];
}

// ---------------------------------------------------------------------------
// Kernel 3: loss = mean(log(s0+s1) - pos)
// ---------------------------------------------------------------------------
__global__ void __launch_bounds__(256) finalize_kernel(float* __restrict__ out) {
    __shared__ float sm[256];
    float acc = 0.f;
    for (int i = threadIdx.x; i < BATCH; i += 256)
        acc += __logf(g_s[0][i] + g_s[1][i]) - g_pos[i];
    sm[threadIdx.x] = acc;
    __syncthreads();
#pragma unroll
    for (int w = 128; w > 0; w >>= 1) {
        if (threadIdx.x < w) sm[threadIdx.x] += sm[threadIdx.x + w];
        __syncthreads();
    }
    if (threadIdx.x == 0) out[0] = sm[0] * (1.0f / (float)BATCH);
}

// ---------------------------------------------------------------------------
extern "C" void kernel_launch(void* const* d_in, const int* in_sizes, int n_in,
                              void* d_out, int out_size) {
    const float* u = (const float*)d_in[0];
    const float* p = (const float*)d_in[1];
    float* out = (float*)d_out;

    cudaFuncSetAttribute(simlse_kernel, cudaFuncAttributeMaxDynamicSharedMemorySize, SMEM_TOTAL);

    norm_pos_kernel<<<(BATCH * 32) / 256, 256>>>(u, p);
    simlse_kernel<<<dim3(BATCH / BM, NSPLIT), 256, SMEM_TOTAL>>>();
    finalize_kernel<<<1, 256>>>(out);
}

// round 17
// speedup vs baseline: 1.0070x; 1.0019x over previous
#include <cuda_runtime.h>
#include <cuda_bf16.h>
#include <cstdint>

// Problem shape (fixed by setup_inputs): B=8192 rows, D=256 dim.
#define BATCH 8192
#define DIM 256
#define INV_T 5.0f

#define BM 128
#define BN 128
#define NSPLIT 2
#define COLS_PER (BATCH / NSPLIT)   // 4096
#define NB_ITERS (COLS_PER / BN)    // 32
#define LDKB 272                    // bytes/row in smem: 256 data + 16 pad (ldmatrix conflict-free)
#define TILE_BYTES (BM * LDKB)      // 34816
#define SMEM_TOTAL (3 * TILE_BYTES + 1024)

// Scratch (__device__ globals: allocations are forbidden)
__device__ uint8_t g_ub[BATCH * DIM];   // normalized u * INV_T, e4m3
__device__ uint8_t g_pb[BATCH * DIM];   // normalized p, e4m3
__device__ float g_pos[BATCH];          // diagonal sim/T (exact fp32 path)
__device__ float g_s[NSPLIT][BATCH];    // partial sum-exp per row

// ---------------------------------------------------------------------------
// PTX helpers
// ---------------------------------------------------------------------------
__device__ __forceinline__ uint32_t smem_u32(const void* p) {
    uint32_t a;
    asm("{ .reg .u64 t; cvta.to.shared.u64 t, %1; cvt.u32.u64 %0, t; }" : "=r"(a) : "l"(p));
    return a;
}
__device__ __forceinline__ void cp16(uint32_t s, const void* g) {
    asm volatile("cp.async.cg.shared.global [%0], [%1], 16;" :: "r"(s), "l"(g));
}
__device__ __forceinline__ void ldmx4(uint32_t* r, uint32_t addr) {
    asm volatile("ldmatrix.sync.aligned.m8n8.x4.shared.b16 {%0,%1,%2,%3}, [%4];"
        : "=r"(r[0]), "=r"(r[1]), "=r"(r[2]), "=r"(r[3]) : "r"(addr));
}
// FP8 e4m3 MMA: m16n8k32, fp32 accumulate. Fragment byte layout is identical
// to the bf16 m16n8k16 case (4B/lane per 8x8 ldmatrix tile), so the same
// ldmatrix addressing feeds it.
__device__ __forceinline__ void mma16832(float* d, const uint32_t* a, uint32_t b0, uint32_t b1) {
    asm volatile("mma.sync.aligned.m16n8k32.row.col.f32.e4m3.e4m3.f32 "
        "{%0,%1,%2,%3}, {%4,%5,%6,%7}, {%8,%9}, {%0,%1,%2,%3};"
        : "+f"(d[0]), "+f"(d[1]), "+f"(d[2]), "+f"(d[3])
        : "r"(a[0]), "r"(a[1]), "r"(a[2]), "r"(a[3]), "r"(b0), "r"(b1));
}

// packed f32x2 fma (Blackwell FFMA2)
__device__ __forceinline__ unsigned long long fma2(unsigned long long a,
                                                   unsigned long long b,
                                                   unsigned long long c) {
    unsigned long long d;
    asm("fma.rn.f32x2 %0, %1, %2, %3;" : "=l"(d) : "l"(a), "l"(b), "l"(c));
    return d;
}
__device__ __forceinline__ unsigned long long pk2(float x) {
    uint32_t u = __float_as_uint(x);
    return ((unsigned long long)u << 32) | u;
}
__device__ __forceinline__ unsigned long long pack2(float lo, float hi) {
    unsigned long long v;
    asm("mov.b64 %0, {%1, %2};" : "=l"(v) : "f"(lo), "f"(hi));
    return v;
}

// Packed exp-and-accumulate on the FMA pipe. Valid |v| <= ~80; here |v| <= ~5.7,
// so no max tracking / overflow handling is needed.
__device__ __forceinline__ void expacc2(unsigned long long v, unsigned long long& s) {
    const unsigned long long K_L2E = pk2(1.4426950408889634f);
    const unsigned long long K_MAG = pk2(12582912.0f);      // 1.5 * 2^23
    const unsigned long long K_N1  = pk2(-1.0f);
    const unsigned long long K_C4  = pk2(0.0096181291f);
    const unsigned long long K_C3  = pk2(0.0555041087f);
    const unsigned long long K_C2  = pk2(0.2402265070f);
    const unsigned long long K_C1  = pk2(0.6931471806f);
    const unsigned long long K_1   = pk2(1.0f);

    unsigned long long z  = fma2(v, K_L2E, K_MAG);   // low 23 bits of each half = round(v*log2e)
    unsigned long long mz = fma2(z, K_N1, K_MAG);    // = -n (exact)
    unsigned long long f  = fma2(v, K_L2E, mz);      // frac in [-0.5, 0.5]
    uint32_t zl, zh;
    asm("mov.b64 {%0, %1}, %2;" : "=r"(zl), "=r"(zh) : "l"(z));
    uint32_t scl = (zl << 23) + 0x3f800000u;         // 2^n bit splice
    uint32_t sch = (zh << 23) + 0x3f800000u;
    unsigned long long sc;
    asm("mov.b64 %0, {%1, %2};" : "=l"(sc) : "r"(scl), "r"(sch));
    unsigned long long p = fma2(K_C4, f, K_C3);
    p = fma2(p, f, K_C2);
    p = fma2(p, f, K_C1);
    p = fma2(p, f, K_1);
    s = fma2(p, sc, s);
}

// ---------------------------------------------------------------------------
// Kernel 1: per-row L2 normalize (fp32) -> e4m3 outputs + fp32 diagonal.
// One warp per row, float4 loads, packed e4m3x4 stores.
// ---------------------------------------------------------------------------
__global__ void __launch_bounds__(256) norm_pos_kernel(const float* __restrict__ uf,
                                                       const float* __restrict__ pf) {
    int row  = (blockIdx.x * blockDim.x + threadIdx.x) >> 5;
    int lane = threadIdx.x & 31;
    if (row >= BATCH) return;

    const float4* ur = (const float4*)(uf + (size_t)row * DIM);
    const float4* pr = (const float4*)(pf + (size_t)row * DIM);
    float4 a0 = ur[lane], a1 = ur[lane + 32];
    float4 b0 = pr[lane], b1 = pr[lane + 32];

    float su = 0.f, sp = 0.f, dp = 0.f;
#define ACC3(a, b) { su = fmaf(a, a, su); sp = fmaf(b, b, sp); dp = fmaf(a, b, dp); }
    ACC3(a0.x, b0.x) ACC3(a0.y, b0.y) ACC3(a0.z, b0.z) ACC3(a0.w, b0.w)
    ACC3(a1.x, b1.x) ACC3(a1.y, b1.y) ACC3(a1.z, b1.z) ACC3(a1.w, b1.w)
#undef ACC3
#pragma unroll
    for (int o = 16; o; o >>= 1) {
        su += __shfl_xor_sync(0xffffffffu, su, o);
        sp += __shfl_xor_sync(0xffffffffu, sp, o);
        dp += __shfl_xor_sync(0xffffffffu, dp, o);
    }
    float iu = 1.0f / fmaxf(sqrtf(su), 1e-12f);
    float ip = 1.0f / fmaxf(sqrtf(sp), 1e-12f);
    float us = iu * INV_T;   // fold 1/T into u so the MMA emits sim/T directly

    // pack 4 floats -> 4 e4m3 bytes (memory order: x,y,z,w)
#define E4M3X4(dst, v, s) do {                                                   \
        uint16_t _lo, _hi;                                                       \
        asm("cvt.rn.satfinite.e4m3x2.f32 %0, %2, %1;" : "=h"(_lo)                \
            : "f"((v).x * (s)), "f"((v).y * (s)));                               \
        asm("cvt.rn.satfinite.e4m3x2.f32 %0, %2, %1;" : "=h"(_hi)                \
            : "f"((v).z * (s)), "f"((v).w * (s)));                               \
        dst = ((uint32_t)_hi << 16) | (uint32_t)_lo;                             \
    } while (0)
    uint32_t w0, w1, v0, v1;
    E4M3X4(w0, a0, us); E4M3X4(w1, a1, us);
    E4M3X4(v0, b0, ip); E4M3X4(v1, b1, ip);
#undef E4M3X4
    uint32_t* uo = (uint32_t*)(g_ub + (size_t)row * DIM);
    uint32_t* po = (uint32_t*)(g_pb + (size_t)row * DIM);
    uo[lane] = w0; uo[lane + 32] = w1;
    po[lane] = v0; po[lane + 32] = v1;
    if (lane == 0) g_pos[row] = dp * iu * ip * INV_T;
}

// ---------------------------------------------------------------------------
// Kernel 2: e4m3 mma.sync GEMM (sim = (u/T)·p^T) fused with packed sum-exp.
// CTA tile 128x128, 8 warps 4(M)x2(N), warp tile 32x64 via m16n8k32.
// A tile resident in smem; B double-buffered full-K via cp.async.
// vs bf16 version: MMA/LDSM instruction counts and smem/L2 traffic all halve.
// ---------------------------------------------------------------------------
__global__ void __launch_bounds__(256) simlse_kernel() {
    extern __shared__ char smem[];
    const uint32_t sA = smem_u32(smem);
    const uint32_t sB = sA + TILE_BYTES;               // two B buffers follow A
    float* rbuf = (float*)(smem + 3 * TILE_BYTES);     // [2][128] cross-warp row sums

    const int tid  = threadIdx.x;
    const int lane = tid & 31;
    const int w    = tid >> 5;
    const int mg   = w >> 1;            // 0..3 : which 32-row slice
    const int ng   = w & 1;             // 0..1 : which 64-col slice
    const int rowBase = blockIdx.x * BM;
    const int colBase = blockIdx.y * COLS_PER;

    // --- cooperative tile loads: 128 rows x 256 bytes, 16B chunks, 8/thread ---
    const uint8_t* gA = g_ub + (size_t)rowBase * DIM;
#pragma unroll
    for (int i = 0; i < 8; i++) {
        int c = tid + i * 256, r = c >> 4, cc = c & 15;
        cp16(sA + (uint32_t)(r * LDKB + cc * 16), gA + (size_t)r * DIM + cc * 16);
    }
    {
        const uint8_t* gB = g_pb + (size_t)colBase * DIM;
#pragma unroll
        for (int i = 0; i < 8; i++) {
            int c = tid + i * 256, r = c >> 4, cc = c & 15;
            cp16(sB + (uint32_t)(r * LDKB + cc * 16), gB + (size_t)r * DIM + cc * 16);
        }
    }
    asm volatile("cp.async.commit_group;");

    // --- ldmatrix base addresses (byte-identical mapping to the bf16 case) ---
    uint32_t aaddr[2];
#pragma unroll
    for (int m = 0; m < 2; m++)
        aaddr[m] = sA + (uint32_t)((mg * 32 + m * 16 + (lane & 15)) * LDKB + (lane >> 4) * 16);
    const int brow = (lane & 7) + ((lane >> 4) << 3);
    const int bcol = ((lane >> 3) & 1) * 16;           // byte offset
    uint32_t boff[4];
#pragma unroll
    for (int fp = 0; fp < 4; fp++)
        boff[fp] = (uint32_t)((ng * 64 + fp * 16 + brow) * LDKB + bcol);

    // packed row-sum accumulators: rows mg*32 + lane/4 + {0,8,16,24}
    unsigned long long spk[4] = {0ull, 0ull, 0ull, 0ull};

    for (int nb = 0; nb < NB_ITERS; nb++) {
        const int cur = nb & 1;
        if (nb + 1 < NB_ITERS) {
            const uint8_t* gB = g_pb + (size_t)(colBase + (nb + 1) * BN) * DIM;
            uint32_t dst = sB + (uint32_t)((cur ^ 1) * TILE_BYTES);
#pragma unroll
            for (int i = 0; i < 8; i++) {
                int c = tid + i * 256, r = c >> 4, cc = c & 15;
                cp16(dst + (uint32_t)(r * LDKB + cc * 16), gB + (size_t)r * DIM + cc * 16);
            }
            asm volatile("cp.async.commit_group;");
            asm volatile("cp.async.wait_group 1;");
        } else {
            asm volatile("cp.async.wait_group 0;");
        }
        __syncthreads();  // tile for this nb visible to all warps

        float acc[2][8][4];
#pragma unroll
        for (int m = 0; m < 2; m++)
#pragma unroll
            for (int f = 0; f < 8; f++)
#pragma unroll
                for (int j = 0; j < 4; j++) acc[m][f][j] = 0.f;

        const uint32_t Bu = sB + (uint32_t)(cur * TILE_BYTES);
#pragma unroll
        for (int ks = 0; ks < 8; ks++) {               // k32 per step: 8 steps cover D=256
            const uint32_t kadv = (uint32_t)(ks * 32); // 32 e4m3 = 32 bytes
            uint32_t a0[4], a1[4];
            ldmx4(a0, aaddr[0] + kadv);
            ldmx4(a1, aaddr[1] + kadv);
#pragma unroll
            for (int fp = 0; fp < 4; fp++) {
                uint32_t b[4];
                ldmx4(b, Bu + boff[fp] + kadv);
                mma16832(acc[0][2 * fp],     a0, b[0], b[1]);
                mma16832(acc[0][2 * fp + 1], a0, b[2], b[3]);
                mma16832(acc[1][2 * fp],     a1, b[0], b[1]);
                mma16832(acc[1][2 * fp + 1], a1, b[2], b[3]);
            }
        }
        __syncthreads();  // all warps done reading before next prefetch overwrites

        // fold this 128-col block into running sum-exp via packed FFMA2.
        // (d0,d1) share row r (adjacent cols); (d2,d3) share row r+8.
#pragma unroll
        for (int m = 0; m < 2; m++)
#pragma unroll
            for (int f = 0; f < 8; f++) {
                expacc2(pack2(acc[m][f][0], acc[m][f][1]), spk[2 * m]);
                expacc2(pack2(acc[m][f][2], acc[m][f][3]), spk[2 * m + 1]);
            }
    }

    // horizontal: each packed acc holds two partial col-sums of the SAME row
    float s[4];
#pragma unroll
    for (int i = 0; i < 4; i++) {
        uint32_t lo, hi;
        asm("mov.b64 {%0, %1}, %2;" : "=r"(lo), "=r"(hi) : "l"(spk[i]));
        s[i] = __uint_as_float(lo) + __uint_as_float(hi);
    }
    // merge across the quad (lanes sharing each row)
#pragma unroll
    for (int i = 0; i < 4; i++) {
        s[i] += __shfl_xor_sync(0xffffffffu, s[i], 1);
        s[i] += __shfl_xor_sync(0xffffffffu, s[i], 2);
    }
    if ((lane & 3) == 0) {
        int r = mg * 32 + (lane >> 2);
        rbuf[ng * 128 + r]      = s[0];
        rbuf[ng * 128 + r + 8]  = s[1];
        rbuf[ng * 128 + r + 16] = s[2];
        rbuf[ng * 128 + r + 24] = s[3];
    }
    __syncthreads();
    if (tid < 128)
        g_s[blockIdx.y][rowBase + tid] = rbuf[tid] + rbuf[128 + tid];
}

// ---------------------------------------------------------------------------
// Kernel 3: loss = mean(log(s0+s1) - pos)
// ---------------------------------------------------------------------------
__global__ void __launch_bounds__(256) finalize_kernel(float* __restrict__ out) {
    __shared__ float sm[256];
    float acc = 0.f;
    for (int i = threadIdx.x; i < BATCH; i += 256)
        acc += __logf(g_s[0][i] + g_s[1][i]) - g_pos[i];
    sm[threadIdx.x] = acc;
    __syncthreads();
#pragma unroll
    for (int w = 128; w > 0; w >>= 1) {
        if (threadIdx.x < w) sm[threadIdx.x] += sm[threadIdx.x + w];
        __syncthreads();
    }
    if (threadIdx.x == 0) out[0] = sm[0] * (1.0f / (float)BATCH);
}

// ---------------------------------------------------------------------------
extern "C" void kernel_launch(void* const* d_in, const int* in_sizes, int n_in,
                              void* d_out, int out_size) {
    const float* u = (const float*)d_in[0];
    const float* p = (const float*)d_in[1];
    float* out = (float*)d_out;

    cudaFuncSetAttribute(simlse_kernel, cudaFuncAttributeMaxDynamicSharedMemorySize, SMEM_TOTAL);

    norm_pos_kernel<<<(BATCH * 32) / 256, 256>>>(u, p);
    simlse_kernel<<<dim3(BATCH / BM, NSPLIT), 256, SMEM_TOTAL>>>();
    finalize_kernel<<<1, 256>>>(out);
}